// round 11
// baseline (speedup 1.0000x reference)
#include <cuda_runtime.h>
#include <cuda_fp16.h>

#define MAXN  100000
#define MAXE  600000
#define NG    512
#define H     128
#define NVOC  4096

// ---- scratch (static __device__ globals; zero-initialized at load,
//      and every replay re-zeroes what it dirtied) ----
__device__ int   g_deg[MAXN];       // zeroed by k_conv1 (after scan use)
__device__ int   g_cursor[MAXN];    // zeroed by k_conv1 (after fill use)
__device__ int   g_rowptr[MAXN + 1];
__device__ uint4 g_edge[MAXE];      // {src, x[src], bits(dis[src]), 0}
__device__ float g_dis[MAXN];
__device__ uint4 g_embW1q[NVOC * 16];           // fp16 table, 1 MB (16 uint4/row)
__device__ uint4 g_h1q[(size_t)MAXN * 16];      // fp16 h1, 25.6 MB
__device__ float g_gsum[NG * H];    // zeroed by k_final after read
__device__ int   g_gcnt[NG];        // zeroed by k_final after read
__device__ int   g_bsum[128];

// ---- fused: embW1 = emb @ W1 (blocks 0-511)  +  degree/graph count (512-1023) ----
__global__ void k_prepcount(const float* __restrict__ emb, const float* __restrict__ W1,
                            const int* __restrict__ dst, int E,
                            const int* __restrict__ batch, int N) {
    __shared__ int hist[NG];
    int b = blockIdx.x;
    if (b < 512) {
        int j = threadIdx.x;
        int r0 = b * 8;
        __half* T = (__half*)g_embW1q;
        for (int r = r0; r < r0 + 8; r++) {
            const float* er = emb + (size_t)r * H;
            float acc = 0.f;
#pragma unroll 8
            for (int k = 0; k < H; k++) acc = fmaf(__ldg(er + k), W1[k * H + j], acc);
            T[(size_t)r * H + j] = __float2half_rn(acc);
        }
    } else {
        int bc = b - 512;
        for (int i = threadIdx.x; i < NG; i += 128) hist[i] = 0;
        __syncthreads();
        int i0 = bc * 128 + threadIdx.x;
        int stride = 512 * 128;
        for (int e = i0; e < E; e += stride) atomicAdd(&g_deg[dst[e]], 1);
        for (int v = i0; v < N; v += stride) atomicAdd(&hist[batch[v]], 1);
        __syncthreads();
        for (int i = threadIdx.x; i < NG; i += 128)
            if (hist[i]) atomicAdd(&g_gcnt[i], hist[i]);
    }
}

// ---- scan phase A: per-block sums ----
__global__ void k_scanA(int N) {
    __shared__ int s[1024];
    int i = blockIdx.x * 1024 + threadIdx.x;
    int v = (i < N) ? g_deg[i] : 0;
    s[threadIdx.x] = v;
    __syncthreads();
    for (int off = 512; off > 0; off >>= 1) {
        if (threadIdx.x < off) s[threadIdx.x] += s[threadIdx.x + off];
        __syncthreads();
    }
    if (threadIdx.x == 0) g_bsum[blockIdx.x] = s[0];
}

// ---- scan phase C (inlined cross-block prefix): deg -> rowptr, dis ----
__global__ void k_scanC(int N, int E) {
    __shared__ int s[1024];
    __shared__ int sprefix;
    int t = threadIdx.x;
    int b = blockIdx.x;
    if (t == 0) sprefix = 0;
    int i = b * 1024 + t;
    int v = (i < N) ? g_deg[i] : 0;
    s[t] = v;
    __syncthreads();
    if (t < b) atomicAdd(&sprefix, g_bsum[t]);
    for (int off = 1; off < 1024; off <<= 1) {
        int u = (t >= off) ? s[t - off] : 0;
        __syncthreads();
        s[t] += u;
        __syncthreads();
    }
    if (i < N) {
        g_rowptr[i] = sprefix + s[t] - v;
        g_dis[i] = rsqrtf((float)(v + 1));   // +1 self-loop
    }
    if (i == 0) g_rowptr[N] = E;
}

// ---- fill CSR: one packed 16B record per edge ----
__global__ void k_fill(const int* __restrict__ src, const int* __restrict__ dst,
                       const int* __restrict__ x, int E) {
    int i0 = blockIdx.x * blockDim.x + threadIdx.x;
    int stride = gridDim.x * blockDim.x;
    for (int e = i0; e < E; e += stride) {
        int d = dst[e];
        int s = src[e];
        int pos = atomicAdd(&g_cursor[d], 1);
        int idx = g_rowptr[d] + pos;
        uint4 rec;
        rec.x = (unsigned)s;
        rec.y = (unsigned)x[s];
        rec.z = __float_as_uint(g_dis[s]);
        rec.w = 0u;
        g_edge[idx] = rec;
    }
}

__device__ __forceinline__ void fma_row8(uint4 u, float w, float* a) {
    __half2* h = (__half2*)&u;
#pragma unroll
    for (int k = 0; k < 4; k++) {
        float2 f = __half22float2(h[k]);
        a[2 * k]     = fmaf(w, f.x, a[2 * k]);
        a[2 * k + 1] = fmaf(w, f.y, a[2 * k + 1]);
    }
}

// ---- conv1: half-warp per node (16 lanes x uint4). Also re-zeroes deg/cursor. ----
__global__ void k_conv1(const int* __restrict__ x, const float* __restrict__ b1, int N) {
    int gw = (blockIdx.x * blockDim.x + threadIdx.x) >> 5;
    int lane = threadIdx.x & 31;
    int half = lane >> 4, l = lane & 15;
    int v = gw * 2 + half;
    bool act = (v < N);
    int vc = act ? v : (N - 1);
    float dv = g_dis[vc];
    const uint4* T = g_embW1q;

    float a[8] = {0.f, 0.f, 0.f, 0.f, 0.f, 0.f, 0.f, 0.f};
    uint4 us = __ldg(&T[(size_t)__ldg(x + vc) * 16 + l]);
    fma_row8(us, dv * dv, a);

    int e = g_rowptr[vc], e1 = act ? g_rowptr[vc + 1] : e;
    for (; e + 3 < e1; e += 4) {
        uint4 r0 = __ldg(&g_edge[e]);
        uint4 r1 = __ldg(&g_edge[e + 1]);
        uint4 r2 = __ldg(&g_edge[e + 2]);
        uint4 r3 = __ldg(&g_edge[e + 3]);
        uint4 u0 = __ldg(&T[(size_t)r0.y * 16 + l]);
        uint4 u1 = __ldg(&T[(size_t)r1.y * 16 + l]);
        uint4 u2 = __ldg(&T[(size_t)r2.y * 16 + l]);
        uint4 u3 = __ldg(&T[(size_t)r3.y * 16 + l]);
        fma_row8(u0, dv * __uint_as_float(r0.z), a);
        fma_row8(u1, dv * __uint_as_float(r1.z), a);
        fma_row8(u2, dv * __uint_as_float(r2.z), a);
        fma_row8(u3, dv * __uint_as_float(r3.z), a);
    }
    for (; e < e1; e++) {
        uint4 r0 = __ldg(&g_edge[e]);
        uint4 u0 = __ldg(&T[(size_t)r0.y * 16 + l]);
        fma_row8(u0, dv * __uint_as_float(r0.z), a);
    }
    if (act) {
        float4 bb0 = ((const float4*)b1)[2 * l];
        float4 bb1 = ((const float4*)b1)[2 * l + 1];
        float o0 = fmaxf(a[0] + bb0.x, 0.f), o1 = fmaxf(a[1] + bb0.y, 0.f);
        float o2 = fmaxf(a[2] + bb0.z, 0.f), o3 = fmaxf(a[3] + bb0.w, 0.f);
        float o4 = fmaxf(a[4] + bb1.x, 0.f), o5 = fmaxf(a[5] + bb1.y, 0.f);
        float o6 = fmaxf(a[6] + bb1.z, 0.f), o7 = fmaxf(a[7] + bb1.w, 0.f);
        __half2 p0 = __floats2half2_rn(o0, o1);
        __half2 p1 = __floats2half2_rn(o2, o3);
        __half2 p2 = __floats2half2_rn(o4, o5);
        __half2 p3 = __floats2half2_rn(o6, o7);
        uint4 o;
        o.x = *(unsigned*)&p0; o.y = *(unsigned*)&p1;
        o.z = *(unsigned*)&p2; o.w = *(unsigned*)&p3;
        g_h1q[(size_t)v * 16 + l] = o;
        if (l == 0) { g_deg[v] = 0; g_cursor[v] = 0; }   // re-zero for next replay
    }
}

// ---- conv2 + pooling: half-warp per node-run (batch sorted), unroll 4 ----
__global__ void k_conv2pool(const int* __restrict__ batch, int N) {
    const int NPW = 8;
    int gw = (blockIdx.x * blockDim.x + threadIdx.x) >> 5;
    int lane = threadIdx.x & 31;
    int half = lane >> 4, l = lane & 15;
    int grp = gw * 2 + half;
    int v0 = grp * NPW;
    int v1 = min(v0 + NPW, N);

    float acc[8] = {0.f, 0.f, 0.f, 0.f, 0.f, 0.f, 0.f, 0.f};
    int curg = -1;
    for (int v = v0; v < v1; v++) {
        float dv = g_dis[v];
        float n[8] = {0.f, 0.f, 0.f, 0.f, 0.f, 0.f, 0.f, 0.f};
        uint4 us = __ldg(&g_h1q[(size_t)v * 16 + l]);
        fma_row8(us, dv * dv, n);
        int e = g_rowptr[v], e1 = g_rowptr[v + 1];
        for (; e + 3 < e1; e += 4) {
            uint4 r0 = __ldg(&g_edge[e]);
            uint4 r1 = __ldg(&g_edge[e + 1]);
            uint4 r2 = __ldg(&g_edge[e + 2]);
            uint4 r3 = __ldg(&g_edge[e + 3]);
            uint4 u0 = __ldg(&g_h1q[(size_t)r0.x * 16 + l]);
            uint4 u1 = __ldg(&g_h1q[(size_t)r1.x * 16 + l]);
            uint4 u2 = __ldg(&g_h1q[(size_t)r2.x * 16 + l]);
            uint4 u3 = __ldg(&g_h1q[(size_t)r3.x * 16 + l]);
            fma_row8(u0, dv * __uint_as_float(r0.z), n);
            fma_row8(u1, dv * __uint_as_float(r1.z), n);
            fma_row8(u2, dv * __uint_as_float(r2.z), n);
            fma_row8(u3, dv * __uint_as_float(r3.z), n);
        }
        for (; e < e1; e++) {
            uint4 r0 = __ldg(&g_edge[e]);
            uint4 u0 = __ldg(&g_h1q[(size_t)r0.x * 16 + l]);
            fma_row8(u0, dv * __uint_as_float(r0.z), n);
        }
        int g = batch[v];
        if (g != curg) {
            if (curg >= 0) {
                float* p = g_gsum + curg * H + l * 8;
#pragma unroll
                for (int k = 0; k < 8; k++) atomicAdd(p + k, acc[k]);
            }
            curg = g;
#pragma unroll
            for (int k = 0; k < 8; k++) acc[k] = n[k];
        } else {
#pragma unroll
            for (int k = 0; k < 8; k++) acc[k] += n[k];
        }
    }
    if (curg >= 0) {
        float* p = g_gsum + curg * H + l * 8;
#pragma unroll
        for (int k = 0; k < 8; k++) atomicAdd(p + k, acc[k]);
    }
}

// ---- final: out[g] = (gsum[g] @ W2) / cnt[g] + b2 ; re-zeroes gsum/gcnt ----
__global__ void k_final(const float* __restrict__ W2, const float* __restrict__ b2,
                        float* __restrict__ out) {
    __shared__ float srow[H];
    int g = blockIdx.x, j = threadIdx.x;
    srow[j] = g_gsum[g * H + j];
    int c = g_gcnt[g];
    __syncthreads();
    g_gsum[g * H + j] = 0.f;          // re-zero for next replay
    if (j == 0) g_gcnt[g] = 0;
    float acc = 0.f;
#pragma unroll 8
    for (int k = 0; k < H; k++) acc = fmaf(srow[k], W2[k * H + j], acc);
    out[g * H + j] = (c > 0) ? (acc / (float)c + b2[j]) : 0.f;
}

extern "C" void kernel_launch(void* const* d_in, const int* in_sizes, int n_in,
                              void* d_out, int out_size) {
    const int*   x     = (const int*)d_in[0];
    const int*   ei    = (const int*)d_in[1];
    const int*   batch = (const int*)d_in[2];
    const float* emb   = (const float*)d_in[3];
    const float* W1    = (const float*)d_in[4];
    const float* b1    = (const float*)d_in[5];
    const float* W2    = (const float*)d_in[6];
    const float* b2    = (const float*)d_in[7];
    float* out = (float*)d_out;

    int N = in_sizes[0];
    int E = in_sizes[1] / 2;
    const int* src = ei;
    const int* dst = ei + E;

    k_prepcount<<<1024, 128>>>(emb, W1, dst, E, batch, N);
    int nb = (N + 1023) / 1024;
    k_scanA<<<nb, 1024>>>(N);
    k_scanC<<<nb, 1024>>>(N, E);
    k_fill<<<(E + 255) / 256, 256>>>(src, dst, x, E);
    int w1n = (N + 1) / 2;                               // warps, 2 nodes each
    k_conv1<<<((size_t)w1n * 32 + 255) / 256, 256>>>(x, b1, N);
    int w2n = (N + 15) / 16;                             // warps, 2 groups x NPW=8
    k_conv2pool<<<((size_t)w2n * 32 + 255) / 256, 256>>>(batch, N);
    k_final<<<NG, H>>>(W2, b2, out);
}

// round 12
// speedup vs baseline: 1.0551x; 1.0551x over previous
#include <cuda_runtime.h>
#include <cuda_fp16.h>

#define MAXN  100000
#define MAXE  600000
#define NG    512
#define H     128
#define NVOC  4096

// ---- scratch (static __device__ globals; zero-initialized at load,
//      and every replay leaves them re-zeroed / overwritten) ----
__device__ int   g_deg[MAXN];       // re-zeroed by k_conv1
__device__ int   g_cursor[MAXN];    // overwritten by k_scanC each replay
__device__ int   g_rowptr[MAXN + 1];
__device__ uint4 g_edge[MAXE];      // {src, x[src], bits(dis[src]), 0}
__device__ float g_dis[MAXN];
__device__ uint2 g_embW1h[NVOC * 32];           // fp16 table, 1 MB
__device__ uint2 g_h1h[(size_t)MAXN * 32];      // fp16 h1, 25.6 MB
__device__ float g_gsum[NG * H];    // re-zeroed by k_final after read
__device__ int   g_gcnt[NG];        // re-zeroed by k_final after read
__device__ int   g_bsum[128];

// ---- fused: embW1 = emb @ W1 (blocks 0-511)  +  degree/graph count (512-1023) ----
__global__ void k_prepcount(const float* __restrict__ emb, const float* __restrict__ W1,
                            const int* __restrict__ dst, int E,
                            const int* __restrict__ batch, int N) {
    __shared__ int hist[NG];
    int b = blockIdx.x;
    if (b < 512) {
        int j = threadIdx.x;
        int r0 = b * 8;
        __half* T = (__half*)g_embW1h;
        for (int r = r0; r < r0 + 8; r++) {
            const float* er = emb + (size_t)r * H;
            float acc = 0.f;
#pragma unroll 8
            for (int k = 0; k < H; k++) acc = fmaf(__ldg(er + k), W1[k * H + j], acc);
            T[(size_t)r * H + j] = __float2half_rn(acc);
        }
    } else {
        int bc = b - 512;
        for (int i = threadIdx.x; i < NG; i += 128) hist[i] = 0;
        __syncthreads();
        int i0 = bc * 128 + threadIdx.x;
        int stride = 512 * 128;
        for (int e = i0; e < E; e += stride) atomicAdd(&g_deg[dst[e]], 1);
        for (int v = i0; v < N; v += stride) atomicAdd(&hist[batch[v]], 1);
        __syncthreads();
        for (int i = threadIdx.x; i < NG; i += 128)
            if (hist[i]) atomicAdd(&g_gcnt[i], hist[i]);
    }
}

// ---- scan phase A: per-block sums ----
__global__ void k_scanA(int N) {
    __shared__ int s[1024];
    int i = blockIdx.x * 1024 + threadIdx.x;
    int v = (i < N) ? g_deg[i] : 0;
    s[threadIdx.x] = v;
    __syncthreads();
    for (int off = 512; off > 0; off >>= 1) {
        if (threadIdx.x < off) s[threadIdx.x] += s[threadIdx.x + off];
        __syncthreads();
    }
    if (threadIdx.x == 0) g_bsum[blockIdx.x] = s[0];
}

// ---- scan phase C: deg -> rowptr (+cursor copy), dis ----
__global__ void k_scanC(int N, int E) {
    __shared__ int s[1024];
    __shared__ int sprefix;
    int t = threadIdx.x;
    int b = blockIdx.x;
    if (t == 0) sprefix = 0;
    int i = b * 1024 + t;
    int v = (i < N) ? g_deg[i] : 0;
    s[t] = v;
    __syncthreads();
    if (t < b) atomicAdd(&sprefix, g_bsum[t]);
    for (int off = 1; off < 1024; off <<= 1) {
        int u = (t >= off) ? s[t - off] : 0;
        __syncthreads();
        s[t] += u;
        __syncthreads();
    }
    if (i < N) {
        int rp = sprefix + s[t] - v;
        g_rowptr[i] = rp;
        g_cursor[i] = rp;                        // fill's allocator starts here
        g_dis[i] = rsqrtf((float)(v + 1));       // +1 self-loop
    }
    if (i == 0) g_rowptr[N] = E;
}

// ---- fill CSR: single atomic gives the slot directly ----
__global__ void k_fill(const int* __restrict__ src, const int* __restrict__ dst,
                       const int* __restrict__ x, int E) {
    int i0 = blockIdx.x * blockDim.x + threadIdx.x;
    int stride = gridDim.x * blockDim.x;
    for (int e = i0; e < E; e += stride) {
        int d = dst[e];
        int s = src[e];
        int idx = atomicAdd(&g_cursor[d], 1);
        uint4 rec;
        rec.x = (unsigned)s;
        rec.y = (unsigned)x[s];
        rec.z = __float_as_uint(g_dis[s]);
        rec.w = 0u;
        g_edge[idx] = rec;
    }
}

__device__ __forceinline__ void fma_row(uint2 u, float w,
                                        float& ax, float& ay, float& az, float& aw) {
    float2 f0 = __half22float2(*(__half2*)&u.x);
    float2 f1 = __half22float2(*(__half2*)&u.y);
    ax = fmaf(w, f0.x, ax); ay = fmaf(w, f0.y, ay);
    az = fmaf(w, f1.x, az); aw = fmaf(w, f1.y, aw);
}

// ---- conv1: warp per node, uint2 lanes, unroll 4; re-zeroes deg ----
__global__ void k_conv1(const int* __restrict__ x, const float* __restrict__ b1, int N) {
    int v = (blockIdx.x * blockDim.x + threadIdx.x) >> 5;
    int lane = threadIdx.x & 31;
    if (v >= N) return;
    float dv = g_dis[v];
    const uint2* T = g_embW1h;

    uint2 us = __ldg(&T[(size_t)__ldg(x + v) * 32 + lane]);
    float ax = 0.f, ay = 0.f, az = 0.f, aw = 0.f;
    fma_row(us, dv * dv, ax, ay, az, aw);

    int e = g_rowptr[v], e1 = g_rowptr[v + 1];
    for (; e + 3 < e1; e += 4) {
        uint4 r0 = __ldg(&g_edge[e]);
        uint4 r1 = __ldg(&g_edge[e + 1]);
        uint4 r2 = __ldg(&g_edge[e + 2]);
        uint4 r3 = __ldg(&g_edge[e + 3]);
        uint2 u0 = __ldg(&T[(size_t)r0.y * 32 + lane]);
        uint2 u1 = __ldg(&T[(size_t)r1.y * 32 + lane]);
        uint2 u2 = __ldg(&T[(size_t)r2.y * 32 + lane]);
        uint2 u3 = __ldg(&T[(size_t)r3.y * 32 + lane]);
        fma_row(u0, dv * __uint_as_float(r0.z), ax, ay, az, aw);
        fma_row(u1, dv * __uint_as_float(r1.z), ax, ay, az, aw);
        fma_row(u2, dv * __uint_as_float(r2.z), ax, ay, az, aw);
        fma_row(u3, dv * __uint_as_float(r3.z), ax, ay, az, aw);
    }
    for (; e < e1; e++) {
        uint4 r0 = __ldg(&g_edge[e]);
        uint2 u0 = __ldg(&T[(size_t)r0.y * 32 + lane]);
        fma_row(u0, dv * __uint_as_float(r0.z), ax, ay, az, aw);
    }
    float4 bb = ((const float4*)b1)[lane];
    float ox = fmaxf(ax + bb.x, 0.f), oy = fmaxf(ay + bb.y, 0.f);
    float oz = fmaxf(az + bb.z, 0.f), ow = fmaxf(aw + bb.w, 0.f);
    __half2 p0 = __floats2half2_rn(ox, oy);
    __half2 p1 = __floats2half2_rn(oz, ow);
    uint2 o;
    o.x = *(unsigned*)&p0; o.y = *(unsigned*)&p1;
    g_h1h[(size_t)v * 32 + lane] = o;
    if (lane == 0) g_deg[v] = 0;      // re-zero for next replay
}

// ---- conv2 + pooling: warp per NPW=8 node run (batch sorted), unroll 4 ----
__global__ void k_conv2pool(const int* __restrict__ batch, int N) {
    const int NPW = 8;
    int gw = (blockIdx.x * blockDim.x + threadIdx.x) >> 5;
    int lane = threadIdx.x & 31;
    int v0 = gw * NPW;
    if (v0 >= N) return;
    int v1 = min(v0 + NPW, N);
    const uint2* Hm = g_h1h;

    float gx = 0.f, gy = 0.f, gz = 0.f, gwv = 0.f;
    int curg = -1;
    for (int v = v0; v < v1; v++) {
        float dv = g_dis[v];
        float nx = 0.f, ny = 0.f, nz = 0.f, nw = 0.f;
        uint2 us = __ldg(&Hm[(size_t)v * 32 + lane]);
        fma_row(us, dv * dv, nx, ny, nz, nw);
        int e = g_rowptr[v], e1 = g_rowptr[v + 1];
        for (; e + 3 < e1; e += 4) {
            uint4 r0 = __ldg(&g_edge[e]);
            uint4 r1 = __ldg(&g_edge[e + 1]);
            uint4 r2 = __ldg(&g_edge[e + 2]);
            uint4 r3 = __ldg(&g_edge[e + 3]);
            uint2 u0 = __ldg(&Hm[(size_t)r0.x * 32 + lane]);
            uint2 u1 = __ldg(&Hm[(size_t)r1.x * 32 + lane]);
            uint2 u2 = __ldg(&Hm[(size_t)r2.x * 32 + lane]);
            uint2 u3 = __ldg(&Hm[(size_t)r3.x * 32 + lane]);
            fma_row(u0, dv * __uint_as_float(r0.z), nx, ny, nz, nw);
            fma_row(u1, dv * __uint_as_float(r1.z), nx, ny, nz, nw);
            fma_row(u2, dv * __uint_as_float(r2.z), nx, ny, nz, nw);
            fma_row(u3, dv * __uint_as_float(r3.z), nx, ny, nz, nw);
        }
        for (; e < e1; e++) {
            uint4 r0 = __ldg(&g_edge[e]);
            uint2 u0 = __ldg(&Hm[(size_t)r0.x * 32 + lane]);
            fma_row(u0, dv * __uint_as_float(r0.z), nx, ny, nz, nw);
        }
        int g = batch[v];
        if (g != curg) {
            if (curg >= 0) {
                float* p = g_gsum + curg * H + lane * 4;
                atomicAdd(p, gx); atomicAdd(p + 1, gy);
                atomicAdd(p + 2, gz); atomicAdd(p + 3, gwv);
            }
            curg = g; gx = nx; gy = ny; gz = nz; gwv = nw;
        } else {
            gx += nx; gy += ny; gz += nz; gwv += nw;
        }
    }
    if (curg >= 0) {
        float* p = g_gsum + curg * H + lane * 4;
        atomicAdd(p, gx); atomicAdd(p + 1, gy);
        atomicAdd(p + 2, gz); atomicAdd(p + 3, gwv);
    }
}

// ---- final: out[g] = (gsum[g] @ W2) / cnt[g] + b2 ; re-zeroes gsum/gcnt ----
__global__ void k_final(const float* __restrict__ W2, const float* __restrict__ b2,
                        float* __restrict__ out) {
    __shared__ float srow[H];
    int g = blockIdx.x, j = threadIdx.x;
    srow[j] = g_gsum[g * H + j];
    int c = g_gcnt[g];
    __syncthreads();
    g_gsum[g * H + j] = 0.f;          // re-zero for next replay
    if (j == 0) g_gcnt[g] = 0;
    float acc = 0.f;
#pragma unroll 8
    for (int k = 0; k < H; k++) acc = fmaf(srow[k], W2[k * H + j], acc);
    out[g * H + j] = (c > 0) ? (acc / (float)c + b2[j]) : 0.f;
}

extern "C" void kernel_launch(void* const* d_in, const int* in_sizes, int n_in,
                              void* d_out, int out_size) {
    const int*   x     = (const int*)d_in[0];
    const int*   ei    = (const int*)d_in[1];
    const int*   batch = (const int*)d_in[2];
    const float* emb   = (const float*)d_in[3];
    const float* W1    = (const float*)d_in[4];
    const float* b1    = (const float*)d_in[5];
    const float* W2    = (const float*)d_in[6];
    const float* b2    = (const float*)d_in[7];
    float* out = (float*)d_out;

    int N = in_sizes[0];
    int E = in_sizes[1] / 2;
    const int* src = ei;
    const int* dst = ei + E;

    k_prepcount<<<1024, 128>>>(emb, W1, dst, E, batch, N);
    int nb = (N + 1023) / 1024;
    k_scanA<<<nb, 1024>>>(N);
    k_scanC<<<nb, 1024>>>(N, E);
    k_fill<<<(E + 255) / 256, 256>>>(src, dst, x, E);
    k_conv1<<<((size_t)N * 32 + 255) / 256, 256>>>(x, b1, N);
    int w2n = (N + 7) / 8;
    k_conv2pool<<<((size_t)w2n * 32 + 255) / 256, 256>>>(batch, N);
    k_final<<<NG, H>>>(W2, b2, out);
}